// round 2
// baseline (speedup 1.0000x reference)
#include <cuda_runtime.h>
#include <math.h>

#define BB   4
#define SS   512
#define HH   256
#define VV   32000
#define MM   (BB*SS)     // 2048
#define NCTA 128

// ---------------- device scratch (no allocation anywhere) ----------------
__device__ float        g_embT[HH * MM];           // [k][bt]              2 MB
__device__ float        g_xp[(size_t)MM * 768];    // [bt][row]            6 MB
__device__ float        g_hs[(SS + 1) * BB * HH];  // [t][b][h], slot0=h_{-1}
__device__ float        g_hsR[(size_t)MM * HH];    // [bt][h] for GEMM     2 MB
__device__ unsigned int g_counter;

// ---------------- kernel A: gather emb -> transposed, init state ----------
__global__ void gather_kernel(const int* __restrict__ x,
                              const float* __restrict__ emb)
{
    const int bt  = blockIdx.x;
    const int tid = threadIdx.x;             // 0..63
    const int tok = x[bt];
    const float4 v = *(const float4*)(emb + (size_t)tok * HH + tid * 4);
    const int k = tid * 4;
    g_embT[(k + 0) * MM + bt] = v.x;
    g_embT[(k + 1) * MM + bt] = v.y;
    g_embT[(k + 2) * MM + bt] = v.z;
    g_embT[(k + 3) * MM + bt] = v.w;
    if (bt == 0) {
        const float4 z4 = make_float4(0.f, 0.f, 0.f, 0.f);
        for (int i = tid; i < (BB * HH) / 4; i += 64)
            ((float4*)g_hs)[i] = z4;
        if (tid == 0) g_counter = 0u;
    }
}

// ---------------- kernel B: input projection xp = emb @ W_ih^T + b_ih -----
// grid (8 bt-tiles, 48 row-groups) x 256
__global__ void __launch_bounds__(256) inproj_kernel(
    const float* __restrict__ W_ih, const float* __restrict__ b_ih)
{
    __shared__ float sW[16 * 256];
    const int r0 = blockIdx.y * 16;
    const int bt = blockIdx.x * 256 + threadIdx.x;
    for (int i = threadIdx.x; i < 16 * 256; i += 256)
        sW[i] = W_ih[(size_t)r0 * 256 + i];
    __syncthreads();

    float acc[16];
#pragma unroll
    for (int ri = 0; ri < 16; ri++) acc[ri] = 0.f;

#pragma unroll 4
    for (int k = 0; k < HH; k++) {
        const float e = g_embT[k * MM + bt];
#pragma unroll
        for (int ri = 0; ri < 16; ri++)
            acc[ri] += e * sW[ri * 256 + k];
    }
    float* o = g_xp + (size_t)bt * 768 + r0;
#pragma unroll
    for (int ri = 0; ri < 16; ri++)
        o[ri] = acc[ri] + b_ih[r0 + ri];
}

// ---------------- kernel C: GRU recurrence -------------------------------
// 128 CTAs x 256 thr; CTA owns hidden columns col0, col0+1.
__global__ void __launch_bounds__(256, 1) gru_kernel(
    const float* __restrict__ W_hh, const float* __restrict__ b_hh)
{
    __shared__ float sWhh[6 * 256];   // [row(c*3+g)][k]
    __shared__ float sh[BB * HH];     // h_{t-1}
    __shared__ float shp[24];
    __shared__ float sxp[24];

    const int tid  = threadIdx.x;
    const int col0 = blockIdx.x * 2;

    for (int i = tid; i < 6 * 256; i += 256) {
        const int r = i >> 8;               // 0..5
        const int c = r / 3, g = r % 3;
        sWhh[i] = W_hh[(size_t)(g * HH + col0 + c) * HH + (i & 255)];
    }

    float bhr = 0.f, bhz = 0.f, bhn = 0.f;
    int gc = 0, gb = 0, gcol = 0;
    if (tid < 8) {
        gc = tid >> 2; gb = tid & 3; gcol = col0 + gc;
        bhr = b_hh[0 * HH + gcol];
        bhz = b_hh[1 * HH + gcol];
        bhn = b_hh[2 * HH + gcol];
    }
    const int dot   = tid >> 3;   // 0..23 for tid<192
    const int lane8 = tid & 7;
    const int drow  = dot >> 2;   // c*3+g
    const int db    = dot & 3;    // batch
    __syncthreads();

    for (int t = 1; t <= SS; t++) {
        if (tid == 0 && t > 1) {
            const unsigned target = (unsigned)NCTA * (unsigned)(t - 1);
            unsigned v;
            do {
                asm volatile("ld.acquire.gpu.u32 %0, [%1];"
                             : "=r"(v) : "l"(&g_counter) : "memory");
            } while (v < target);
        }
        __syncthreads();

        ((float4*)sh)[tid] = ((const float4*)(g_hs + (size_t)(t - 1) * (BB * HH)))[tid];
        if (tid < 24) {
            const int b = tid & 3, rr = tid >> 2;
            const int c = rr / 3, g = rr % 3;
            sxp[tid] = g_xp[(size_t)(b * SS + t - 1) * 768 + g * HH + col0 + c];
        }
        __syncthreads();

        if (tid < 192) {
            const float* hrow = sh   + db   * HH;
            const float* wrow = sWhh + drow * HH;
            float s = 0.f;
#pragma unroll
            for (int i = 0; i < 8; i++) {
                const int k = lane8 * 4 + i * 32;
                const float4 h4 = *(const float4*)(hrow + k);
                const float4 w4 = *(const float4*)(wrow + k);
                s += h4.x * w4.x + h4.y * w4.y + h4.z * w4.z + h4.w * w4.w;
            }
            s += __shfl_down_sync(0xffffffffu, s, 4, 8);
            s += __shfl_down_sync(0xffffffffu, s, 2, 8);
            s += __shfl_down_sync(0xffffffffu, s, 1, 8);
            if (lane8 == 0) shp[dot] = s;
        }
        __syncthreads();

        if (tid < 8) {
            const float hr = shp[(gc * 3 + 0) * 4 + gb] + bhr;
            const float hz = shp[(gc * 3 + 1) * 4 + gb] + bhz;
            const float hn = shp[(gc * 3 + 2) * 4 + gb] + bhn;
            const float xr = sxp[(gc * 3 + 0) * 4 + gb];
            const float xz = sxp[(gc * 3 + 1) * 4 + gb];
            const float xn = sxp[(gc * 3 + 2) * 4 + gb];
            const float r  = 1.f / (1.f + expf(-(xr + hr)));
            const float z  = 1.f / (1.f + expf(-(xz + hz)));
            const float n  = tanhf(xn + r * hn);
            const float ho = sh[gb * HH + gcol];
            const float hnew = (1.f - z) * n + z * ho;
            g_hs[(size_t)t * (BB * HH) + gb * HH + gcol] = hnew;
            g_hsR[(size_t)(gb * SS + t - 1) * HH + gcol] = hnew;
        }
        __syncthreads();
        if (tid == 0) { __threadfence(); atomicAdd(&g_counter, 1u); }
    }
}

// ---------------- kernel D: output GEMM (TF32 mma) + bias + mask ----------
__device__ __forceinline__ unsigned f2tf(float f) {
    unsigned r;
    asm("cvt.rna.tf32.f32 %0, %1;" : "=r"(r) : "f"(f));
    return r;
}

__global__ void __launch_bounds__(256) gemm_out_kernel(
    const float* __restrict__ Wout, const float* __restrict__ bout,
    const int* __restrict__ x, float* __restrict__ out)
{
    __shared__ unsigned sA[128 * 36];   // [m][k] tf32, pad 36
    __shared__ unsigned sB[128 * 36];   // [n][k] tf32

    const int m0   = blockIdx.y * 128;
    const int n0   = blockIdx.x * 128;
    const int tid  = threadIdx.x;
    const int lane = tid & 31;
    const int wid  = tid >> 5;          // 0..7
    const int wm   = wid & 3;           // 4 warps along m
    const int wn   = wid >> 2;          // 2 warps along n
    const int gid  = lane >> 2;
    const int tig  = lane & 3;

    float acc[2][8][4];
#pragma unroll
    for (int mi = 0; mi < 2; mi++)
#pragma unroll
        for (int ni = 0; ni < 8; ni++)
#pragma unroll
            for (int q = 0; q < 4; q++) acc[mi][ni][q] = 0.f;

    const int srow = tid >> 3;          // 0..31
    const int skq  = (tid & 7) * 4;     // 0..28

    for (int k0 = 0; k0 < HH; k0 += 32) {
        __syncthreads();
#pragma unroll
        for (int rr = 0; rr < 4; rr++) {
            const int row = rr * 32 + srow;
            const float4 a4 = *(const float4*)(g_hsR + (size_t)(m0 + row) * HH + k0 + skq);
            unsigned* pa = &sA[row * 36 + skq];
            pa[0] = f2tf(a4.x); pa[1] = f2tf(a4.y); pa[2] = f2tf(a4.z); pa[3] = f2tf(a4.w);
            const float4 b4 = *(const float4*)(Wout + (size_t)(n0 + row) * HH + k0 + skq);
            unsigned* pb = &sB[row * 36 + skq];
            pb[0] = f2tf(b4.x); pb[1] = f2tf(b4.y); pb[2] = f2tf(b4.z); pb[3] = f2tf(b4.w);
        }
        __syncthreads();

#pragma unroll
        for (int ks = 0; ks < 4; ks++) {
            const int k8 = ks * 8;
            unsigned af[2][4];
#pragma unroll
            for (int mi = 0; mi < 2; mi++) {
                const int base = wm * 32 + mi * 16;
                af[mi][0] = sA[(base + gid) * 36 + k8 + tig];
                af[mi][1] = sA[(base + gid + 8) * 36 + k8 + tig];
                af[mi][2] = sA[(base + gid) * 36 + k8 + tig + 4];
                af[mi][3] = sA[(base + gid + 8) * 36 + k8 + tig + 4];
            }
#pragma unroll
            for (int ni = 0; ni < 8; ni++) {
                const int nb = wn * 64 + ni * 8;
                const unsigned b0 = sB[(nb + gid) * 36 + k8 + tig];
                const unsigned b1 = sB[(nb + gid) * 36 + k8 + tig + 4];
#pragma unroll
                for (int mi = 0; mi < 2; mi++) {
                    asm volatile(
                        "mma.sync.aligned.m16n8k8.row.col.f32.tf32.tf32.f32 "
                        "{%0,%1,%2,%3}, {%4,%5,%6,%7}, {%8,%9}, {%0,%1,%2,%3};"
                        : "+f"(acc[mi][ni][0]), "+f"(acc[mi][ni][1]),
                          "+f"(acc[mi][ni][2]), "+f"(acc[mi][ni][3])
                        : "r"(af[mi][0]), "r"(af[mi][1]), "r"(af[mi][2]), "r"(af[mi][3]),
                          "r"(b0), "r"(b1));
                }
            }
        }
    }

    // epilogue: bias + symbolic mask + store
#pragma unroll
    for (int mi = 0; mi < 2; mi++) {
        const int rbase = m0 + wm * 32 + mi * 16;
#pragma unroll
        for (int half = 0; half < 2; half++) {
            const int row = rbase + gid + half * 8;    // bt
            const int t   = row & (SS - 1);
            const bool pz = (t > 0) && (x[row - 1] == 0);
#pragma unroll
            for (int ni = 0; ni < 8; ni++) {
                const int col = n0 + wn * 64 + ni * 8 + tig * 2;
                float v0 = acc[mi][ni][half * 2 + 0] + bout[col];
                float v1 = acc[mi][ni][half * 2 + 1] + bout[col + 1];
                if (pz) {
                    if (col >= 3)     v0 = -INFINITY;
                    if (col + 1 >= 3) v1 = -INFINITY;
                }
                *(float2*)(out + (size_t)row * VV + col) = make_float2(v0, v1);
            }
        }
    }
}

// ---------------- launch ---------------------------------------------------
extern "C" void kernel_launch(void* const* d_in, const int* in_sizes, int n_in,
                              void* d_out, int out_size)
{
    const int*   x     = (const int*)  d_in[0];
    const float* emb   = (const float*)d_in[1];
    const float* W_ih  = (const float*)d_in[2];
    const float* W_hh  = (const float*)d_in[3];
    const float* b_ih  = (const float*)d_in[4];
    const float* b_hh  = (const float*)d_in[5];
    const float* W_out = (const float*)d_in[6];
    const float* b_out = (const float*)d_in[7];
    float* out = (float*)d_out;

    gather_kernel<<<MM, 64>>>(x, emb);
    inproj_kernel<<<dim3(MM / 256, 768 / 16), 256>>>(W_ih, b_ih);
    gru_kernel<<<NCTA, 256>>>(W_hh, b_hh);
    gemm_out_kernel<<<dim3(VV / 128, MM / 128), 256>>>(W_out, b_out, x, out);
}

// round 3
// speedup vs baseline: 1.5970x; 1.5970x over previous
#include <cuda_runtime.h>
#include <math.h>

#define BB   4
#define SS   512
#define HH   256
#define VV   32000
#define MM   (BB*SS)     // 2048

// ---------------- device scratch (no allocation anywhere) ----------------
__device__ float g_embT[HH * MM];           // [k][bt]               2 MB
__device__ float g_xp[(size_t)MM * 768];    // [bt][row]             6 MB
__device__ float g_hsR[(size_t)MM * HH];    // [bt][h] for GEMM      2 MB

// ---------------- kernel A: gather emb -> transposed ----------------------
__global__ void gather_kernel(const int* __restrict__ x,
                              const float* __restrict__ emb)
{
    const int bt  = blockIdx.x;
    const int tid = threadIdx.x;             // 0..63
    const int tok = x[bt];
    const float4 v = *(const float4*)(emb + (size_t)tok * HH + tid * 4);
    const int k = tid * 4;
    g_embT[(k + 0) * MM + bt] = v.x;
    g_embT[(k + 1) * MM + bt] = v.y;
    g_embT[(k + 2) * MM + bt] = v.z;
    g_embT[(k + 3) * MM + bt] = v.w;
}

// ---------------- kernel B: xp = emb @ W_ih^T + b_ih ----------------------
__global__ void __launch_bounds__(256) inproj_kernel(
    const float* __restrict__ W_ih, const float* __restrict__ b_ih)
{
    __shared__ float sW[16 * 256];
    const int r0 = blockIdx.y * 16;
    const int bt = blockIdx.x * 256 + threadIdx.x;
    for (int i = threadIdx.x; i < 16 * 256; i += 256)
        sW[i] = W_ih[(size_t)r0 * 256 + i];
    __syncthreads();

    float acc[16];
#pragma unroll
    for (int ri = 0; ri < 16; ri++) acc[ri] = 0.f;

#pragma unroll 4
    for (int k = 0; k < HH; k++) {
        const float e = g_embT[k * MM + bt];
#pragma unroll
        for (int ri = 0; ri < 16; ri++)
            acc[ri] += e * sW[ri * 256 + k];
    }
    float* o = g_xp + (size_t)bt * 768 + r0;
#pragma unroll
    for (int ri = 0; ri < 16; ri++)
        o[ri] = acc[ri] + b_ih[r0 + ri];
}

// ---------------- kernel C: GRU recurrence (cluster version) --------------
// 4 clusters (1 per batch) x 8 CTAs x 384 threads.
// CTA rank owns hidden columns [rank*32, rank*32+32).
// Warp w (of 12): gate g = w>>2, k-chunk kc = w&3, lane = local column.
// W_hh slice lives in registers (64 floats/thread); h broadcast via DSMEM.
__global__ void __launch_bounds__(384, 1) __cluster_dims__(8, 1, 1)
gru_kernel(const float* __restrict__ W_hh, const float* __restrict__ b_hh)
{
    __shared__ float  sh[2][HH];     // double-buffered h for this batch
    __shared__ float4 spart[96];     // partial dots [g*32 + col].kc

    const int tid  = threadIdx.x;
    const int w    = tid >> 5;       // 0..11
    const int lane = tid & 31;
    const int g    = w >> 2;         // gate 0..2
    const int kc   = w & 3;          // k-chunk 0..3
    unsigned rank;
    asm("mov.u32 %0, %%cluster_ctarank;" : "=r"(rank));
    const int batch = blockIdx.x >> 3;
    const int col   = (int)rank * 32 + lane;     // this thread's column (as row owner)

    // persistent W_hh slice in registers: row j = g*256 + col, k in [kc*64, kc*64+64)
    float wreg[64];
    {
        const float* wrow = W_hh + (size_t)(g * HH + col) * HH + kc * 64;
#pragma unroll
        for (int i = 0; i < 64; i++) wreg[i] = wrow[i];
    }

    // gate-thread constants (threads 0..31 handle columns)
    float bhr = 0.f, bhz = 0.f, bhn = 0.f;
    int gcol = 0;
    if (tid < 32) {
        gcol = (int)rank * 32 + tid;
        bhr = b_hh[0 * HH + gcol];
        bhz = b_hh[1 * HH + gcol];
        bhn = b_hh[2 * HH + gcol];
    }

    // init h0 = 0
    if (tid < HH) sh[0][tid] = 0.f;
    __syncthreads();
    asm volatile("barrier.cluster.arrive.aligned;" ::: "memory");
    asm volatile("barrier.cluster.wait.aligned;"   ::: "memory");

    const unsigned sh_addr = (unsigned)__cvta_generic_to_shared(&sh[0][0]);

    for (int t = 1; t <= SS; t++) {
        const int cur = (t - 1) & 1;
        const int nxt = t & 1;

        // xp loads (independent of dots — issued early, consumed after)
        float xr = 0.f, xz = 0.f, xn = 0.f;
        if (tid < 32) {
            const size_t base = (size_t)(batch * SS + t - 1) * 768 + gcol;
            xr = g_xp[base + 0 * HH];
            xz = g_xp[base + 1 * HH];
            xn = g_xp[base + 2 * HH];
        }

        // partial dot: W[g*256+col][kc*64 .. +64) . h[kc*64 .. +64)
        {
            const float* hb = &sh[cur][kc * 64];
            float s = 0.f;
#pragma unroll
            for (int i = 0; i < 64; i += 4) {
                const float4 h4 = *(const float4*)(hb + i);   // warp-broadcast
                s = fmaf(wreg[i + 0], h4.x, s);
                s = fmaf(wreg[i + 1], h4.y, s);
                s = fmaf(wreg[i + 2], h4.z, s);
                s = fmaf(wreg[i + 3], h4.w, s);
            }
            ((float*)&spart[g * 32 + lane])[kc] = s;
        }
        __syncthreads();

        if (tid < 32) {
            const float4 p0 = spart[0 * 32 + tid];
            const float4 p1 = spart[1 * 32 + tid];
            const float4 p2 = spart[2 * 32 + tid];
            const float hr = p0.x + p0.y + p0.z + p0.w + bhr;
            const float hz = p1.x + p1.y + p1.z + p1.w + bhz;
            const float hn = p2.x + p2.y + p2.z + p2.w + bhn;
            const float r  = 1.f / (1.f + expf(-(xr + hr)));
            const float z  = 1.f / (1.f + expf(-(xz + hz)));
            const float n  = tanhf(xn + r * hn);
            const float ho = sh[cur][gcol];
            const float hnew = (1.f - z) * n + z * ho;

            // broadcast h_new into all 8 cluster CTAs' sh[nxt][gcol]
            const unsigned dst = sh_addr + (unsigned)(nxt * HH + gcol) * 4u;
#pragma unroll
            for (int rk = 0; rk < 8; rk++) {
                unsigned rem;
                asm volatile("mapa.shared::cluster.u32 %0, %1, %2;"
                             : "=r"(rem) : "r"(dst), "r"((unsigned)rk));
                asm volatile("st.shared::cluster.f32 [%0], %1;"
                             :: "r"(rem), "f"(hnew) : "memory");
            }
            g_hsR[(size_t)(batch * SS + t - 1) * HH + gcol] = hnew;
        }

        asm volatile("barrier.cluster.arrive.aligned;" ::: "memory");
        asm volatile("barrier.cluster.wait.aligned;"   ::: "memory");
    }
}

// ---------------- kernel D: output GEMM (TF32 mma) + bias + mask ----------
__device__ __forceinline__ unsigned f2tf(float f) {
    unsigned r;
    asm("cvt.rna.tf32.f32 %0, %1;" : "=r"(r) : "f"(f));
    return r;
}

__global__ void __launch_bounds__(256) gemm_out_kernel(
    const float* __restrict__ Wout, const float* __restrict__ bout,
    const int* __restrict__ x, float* __restrict__ out)
{
    __shared__ unsigned sA[128 * 36];   // [m][k] tf32, pad 36
    __shared__ unsigned sB[128 * 36];   // [n][k] tf32

    const int m0   = blockIdx.y * 128;
    const int n0   = blockIdx.x * 128;
    const int tid  = threadIdx.x;
    const int lane = tid & 31;
    const int wid  = tid >> 5;          // 0..7
    const int wm   = wid & 3;           // 4 warps along m
    const int wn   = wid >> 2;          // 2 warps along n
    const int gid  = lane >> 2;
    const int tig  = lane & 3;

    float acc[2][8][4];
#pragma unroll
    for (int mi = 0; mi < 2; mi++)
#pragma unroll
        for (int ni = 0; ni < 8; ni++)
#pragma unroll
            for (int q = 0; q < 4; q++) acc[mi][ni][q] = 0.f;

    const int srow = tid >> 3;          // 0..31
    const int skq  = (tid & 7) * 4;     // 0..28

    for (int k0 = 0; k0 < HH; k0 += 32) {
        __syncthreads();
#pragma unroll
        for (int rr = 0; rr < 4; rr++) {
            const int row = rr * 32 + srow;
            const float4 a4 = *(const float4*)(g_hsR + (size_t)(m0 + row) * HH + k0 + skq);
            unsigned* pa = &sA[row * 36 + skq];
            pa[0] = f2tf(a4.x); pa[1] = f2tf(a4.y); pa[2] = f2tf(a4.z); pa[3] = f2tf(a4.w);
            const float4 b4 = *(const float4*)(Wout + (size_t)(n0 + row) * HH + k0 + skq);
            unsigned* pb = &sB[row * 36 + skq];
            pb[0] = f2tf(b4.x); pb[1] = f2tf(b4.y); pb[2] = f2tf(b4.z); pb[3] = f2tf(b4.w);
        }
        __syncthreads();

#pragma unroll
        for (int ks = 0; ks < 4; ks++) {
            const int k8 = ks * 8;
            unsigned af[2][4];
#pragma unroll
            for (int mi = 0; mi < 2; mi++) {
                const int base = wm * 32 + mi * 16;
                af[mi][0] = sA[(base + gid) * 36 + k8 + tig];
                af[mi][1] = sA[(base + gid + 8) * 36 + k8 + tig];
                af[mi][2] = sA[(base + gid) * 36 + k8 + tig + 4];
                af[mi][3] = sA[(base + gid + 8) * 36 + k8 + tig + 4];
            }
#pragma unroll
            for (int ni = 0; ni < 8; ni++) {
                const int nb = wn * 64 + ni * 8;
                const unsigned b0 = sB[(nb + gid) * 36 + k8 + tig];
                const unsigned b1 = sB[(nb + gid) * 36 + k8 + tig + 4];
#pragma unroll
                for (int mi = 0; mi < 2; mi++) {
                    asm volatile(
                        "mma.sync.aligned.m16n8k8.row.col.f32.tf32.tf32.f32 "
                        "{%0,%1,%2,%3}, {%4,%5,%6,%7}, {%8,%9}, {%0,%1,%2,%3};"
                        : "+f"(acc[mi][ni][0]), "+f"(acc[mi][ni][1]),
                          "+f"(acc[mi][ni][2]), "+f"(acc[mi][ni][3])
                        : "r"(af[mi][0]), "r"(af[mi][1]), "r"(af[mi][2]), "r"(af[mi][3]),
                          "r"(b0), "r"(b1));
                }
            }
        }
    }

    // epilogue: bias + symbolic mask + store
#pragma unroll
    for (int mi = 0; mi < 2; mi++) {
        const int rbase = m0 + wm * 32 + mi * 16;
#pragma unroll
        for (int half = 0; half < 2; half++) {
            const int row = rbase + gid + half * 8;    // bt
            const int t   = row & (SS - 1);
            const bool pz = (t > 0) && (x[row - 1] == 0);
#pragma unroll
            for (int ni = 0; ni < 8; ni++) {
                const int col = n0 + wn * 64 + ni * 8 + tig * 2;
                float v0 = acc[mi][ni][half * 2 + 0] + bout[col];
                float v1 = acc[mi][ni][half * 2 + 1] + bout[col + 1];
                if (pz) {
                    if (col >= 3)     v0 = -INFINITY;
                    if (col + 1 >= 3) v1 = -INFINITY;
                }
                *(float2*)(out + (size_t)row * VV + col) = make_float2(v0, v1);
            }
        }
    }
}

// ---------------- launch ---------------------------------------------------
extern "C" void kernel_launch(void* const* d_in, const int* in_sizes, int n_in,
                              void* d_out, int out_size)
{
    const int*   x     = (const int*)  d_in[0];
    const float* emb   = (const float*)d_in[1];
    const float* W_ih  = (const float*)d_in[2];
    const float* W_hh  = (const float*)d_in[3];
    const float* b_ih  = (const float*)d_in[4];
    const float* b_hh  = (const float*)d_in[5];
    const float* W_out = (const float*)d_in[6];
    const float* b_out = (const float*)d_in[7];
    float* out = (float*)d_out;

    gather_kernel<<<MM, 64>>>(x, emb);
    inproj_kernel<<<dim3(MM / 256, 768 / 16), 256>>>(W_ih, b_ih);
    gru_kernel<<<32, 384>>>(W_hh, b_hh);
    gemm_out_kernel<<<dim3(VV / 128, MM / 128), 256>>>(W_out, b_out, x, out);
}